// round 15
// baseline (speedup 1.0000x reference)
#include <cuda_runtime.h>
#include <cuda_fp16.h>
#include <mma.h>
#include <math.h>

using namespace nvcuda;

#define N_NODES 100000
#define N_EDGES 1600000
#define DIM     128
#define EPSF    1e-12f
#define NBLK    ((N_NODES + 255) / 256)   // 391
#define GTILE   128
#define LDH     136

// block partition for the merged scatter+pack+transpose+zero launch
#define SCAT_BLOCKS 2048
#define PACK_BLOCKS 12500
#define TRAN_BLOCKS 48
#define ZERO_BLOCKS 112
#define MERG_BLOCKS (SCAT_BLOCKS + PACK_BLOCKS + TRAN_BLOCKS + ZERO_BLOCKS)

// ---------------- scratch (__device__ globals, zero-initialized) ---------------
// pack split per space: each 25.6 MB -> L2-resident during its agg pass
__device__ __align__(16) __half g_packe[(size_t)N_NODES * DIM];
__device__ __align__(16) __half g_packb[(size_t)N_NODES * DIM];
__device__ __align__(16) __half g_packs[(size_t)N_NODES * DIM];
__device__ __align__(16) __half g_emean[(size_t)N_NODES * DIM];
__device__ __align__(16) __half g_bmean[(size_t)N_NODES * DIM];
__device__ __align__(16) __half g_smean[(size_t)N_NODES * DIM];
__device__ __align__(16) __half g_Wth [3 * DIM * DIM];          // W^T fp16
__device__ int   g_counts[N_NODES + NBLK];   // [counts | scan status]; re-zeroed per launch
__device__ int   g_rowptr[N_NODES + 1];
__device__ int   g_cursor[N_NODES];
__device__ int   g_csr   [N_EDGES];

// ---------------- helpers ------------------------------------------------------
__device__ __forceinline__ uint2 f4_to_h4(float4 v) {
    __half2 lo = __floats2half2_rn(v.x, v.y);
    __half2 hi = __floats2half2_rn(v.z, v.w);
    uint2 r;
    r.x = *(unsigned*)&lo;
    r.y = *(unsigned*)&hi;
    return r;
}

__device__ __forceinline__ void h4_acc(uint2 u, float4& a) {
    float2 lo = __half22float2(*(__half2*)&u.x);
    float2 hi = __half22float2(*(__half2*)&u.y);
    a.x += lo.x; a.y += lo.y; a.z += hi.x; a.w += hi.y;
}

// fp16 pairwise add (2x HADD2)
__device__ __forceinline__ uint2 h4_add(uint2 a, uint2 b) {
    __half2 ax = *(__half2*)&a.x, ay = *(__half2*)&a.y;
    __half2 bx = *(__half2*)&b.x, by = *(__half2*)&b.y;
    __half2 rx = __hadd2(ax, bx), ry = __hadd2(ay, by);
    uint2 r;
    r.x = *(unsigned*)&rx;
    r.y = *(unsigned*)&ry;
    return r;
}

// ---------------- hist (int4-vectorized, streaming reads) -----------------------
__global__ void hist_kernel(const int4* __restrict__ dst4, int* __restrict__ counts) {
    int i = blockIdx.x * blockDim.x + threadIdx.x;
    int stride = gridDim.x * blockDim.x;
    const int n4 = N_EDGES / 4;   // 400000, exact
    for (int e = i; e < n4; e += stride) {
        int4 d = __ldcs(dst4 + e);
        atomicAdd(counts + d.x, 1);
        atomicAdd(counts + d.y, 1);
        atomicAdd(counts + d.z, 1);
        atomicAdd(counts + d.w, 1);
    }
}

// ---------------- single-kernel decoupled-lookback scan -------------------------
__global__ void __launch_bounds__(256)
scan_lookback(const int* __restrict__ counts, int* __restrict__ rowptr,
              int* __restrict__ cursor, volatile int* status) {
    int b = blockIdx.x, t = threadIdx.x;
    int gid = b * 256 + t;
    int lane = t & 31, wid = t >> 5;
    int v = (gid < N_NODES) ? counts[gid] : 0;

    int x = v;
    #pragma unroll
    for (int o = 1; o < 32; o <<= 1) {
        int y = __shfl_up_sync(0xffffffffu, x, o);
        if (lane >= o) x += y;
    }
    __shared__ int wt[8];
    __shared__ int woff[8];
    __shared__ int s_prefix;
    __shared__ int s_total;
    if (lane == 31) wt[wid] = x;
    __syncthreads();

    if (t == 0) {
        int run = 0;
        #pragma unroll
        for (int i = 0; i < 8; i++) { woff[i] = run; run += wt[i]; }
        s_total = run;
        if (b == 0) {
            status[0] = (run << 2) | 2;
            s_prefix = 0;
        } else {
            status[b] = (run << 2) | 1;
            int running = 0;
            for (int p = b - 1; p >= 0;) {
                int s;
                do { s = status[p]; } while ((s & 3) == 0);
                running += (s >> 2);
                if ((s & 3) == 2) break;
                p--;
            }
            s_prefix = running;
            status[b] = ((running + run) << 2) | 2;
        }
    }
    __syncthreads();

    int ex = x - v + woff[wid] + s_prefix;
    if (gid < N_NODES) { rowptr[gid] = ex; cursor[gid] = ex; }
    if (t == 0 && b == NBLK - 1) rowptr[N_NODES] = s_prefix + s_total;
}

// ---------------- merged: scatter + pack + W transposes + counts re-zero --------
__global__ void __launch_bounds__(256)
scatter_pack_kernel(const int4* __restrict__ src4, const int4* __restrict__ dst4,
                    int* __restrict__ cursor, int* __restrict__ csr,
                    const float* __restrict__ e_emb, const float* __restrict__ b_emb,
                    const float* __restrict__ s_emb,
                    __half* __restrict__ packe, __half* __restrict__ packb,
                    __half* __restrict__ packs,
                    const float* __restrict__ W0, const float* __restrict__ W1,
                    const float* __restrict__ W2, __half* __restrict__ Wt,
                    int* __restrict__ counts) {
    int blk = blockIdx.x;

    if (blk < SCAT_BLOCKS) {
        // ---- CSR scatter, 4 edges per iteration, streaming edge reads ----
        int i = blk * 256 + threadIdx.x;
        int stride = SCAT_BLOCKS * 256;
        const int n4 = N_EDGES / 4;   // exact
        for (int e = i; e < n4; e += stride) {
            int4 s = __ldcs(src4 + e);
            int4 d = __ldcs(dst4 + e);
            csr[atomicAdd(cursor + d.x, 1)] = s.x;
            csr[atomicAdd(cursor + d.y, 1)] = s.y;
            csr[atomicAdd(cursor + d.z, 1)] = s.z;
            csr[atomicAdd(cursor + d.w, 1)] = s.w;
        }
    } else if (blk < SCAT_BLOCKS + PACK_BLOCKS) {
        int lane = threadIdx.x & 31;
        int node = ((blk - SCAT_BLOCKS) * 256 + (int)threadIdx.x) >> 5;
        if (node >= N_NODES) return;

        float4 e = __ldcs((const float4*)e_emb + (size_t)node * 32 + lane);
        float4 b = __ldcs((const float4*)b_emb + (size_t)node * 32 + lane);
        float4 s = __ldcs((const float4*)s_emb + (size_t)node * 32 + lane);

        float nb = b.x*b.x + b.y*b.y + b.z*b.z + b.w*b.w;
        float ns = s.x*s.x + s.y*s.y + s.z*s.z + s.w*s.w;
        #pragma unroll
        for (int o = 16; o; o >>= 1) {
            nb += __shfl_xor_sync(0xffffffffu, nb, o);
            ns += __shfl_xor_sync(0xffffffffu, ns, o);
        }
        float bn_safe = fmaxf(sqrtf(nb), EPSF);
        float bn_cl   = fminf(bn_safe, 1.f - 1e-5f);
        float bsc = atanhf(bn_cl) / bn_safe;
        float ssc = 1.f / fmaxf(sqrtf(ns), EPSF);

        b.x *= bsc; b.y *= bsc; b.z *= bsc; b.w *= bsc;
        s.x *= ssc; s.y *= ssc; s.z *= ssc; s.w *= ssc;

        size_t o = (size_t)node * 32 + lane;
        ((uint2*)packe)[o] = f4_to_h4(e);
        ((uint2*)packb)[o] = f4_to_h4(b);
        ((uint2*)packs)[o] = f4_to_h4(s);
    } else if (blk < SCAT_BLOCKS + PACK_BLOCKS + TRAN_BLOCKS) {
        __shared__ float t[32][33];
        int tb = blk - SCAT_BLOCKS - PACK_BLOCKS;  // 0..47
        int z = tb >> 4;
        int tile = tb & 15;
        const float* W = (z == 0) ? W0 : (z == 1) ? W1 : W2;
        __half* D = Wt + z * DIM * DIM;
        int bx = (tile & 3) * 32, by = (tile >> 2) * 32;
        int x = threadIdx.x & 31, y = threadIdx.x >> 5;   // (32, 8)
        #pragma unroll
        for (int j = 0; j < 32; j += 8)
            t[y + j][x] = W[(by + y + j) * DIM + bx + x];
        __syncthreads();
        #pragma unroll
        for (int j = 0; j < 32; j += 8)
            D[(bx + y + j) * DIM + by + x] = __float2half(t[x][y + j]);
    } else {
        // re-zero counts + scan status for the NEXT graph replay
        int zb = blk - SCAT_BLOCKS - PACK_BLOCKS - TRAN_BLOCKS;   // 0..111
        int i = zb * 256 + threadIdx.x;
        int stride = ZERO_BLOCKS * 256;
        for (int k = i; k < N_NODES + NBLK; k += stride)
            counts[k] = 0;
    }
}

// ---------------- CSR mean-aggregate, ONE space per launch ----------------------
// 25.6 MB gather footprint -> L2-resident. Warp per node, x8 edge unroll
// (8 independent loads in flight; 32 % 8 == 0 so full chunks have no tail).
__global__ void __launch_bounds__(64)
agg_space(const uint2* __restrict__ pk, uint2* __restrict__ mean,
          const int* __restrict__ csr, const int* __restrict__ rp) {
    int lane = threadIdx.x & 31;
    int node = (blockIdx.x * blockDim.x + threadIdx.x) >> 5;
    if (node >= N_NODES) return;

    int beg = __ldg(rp + node), end = __ldg(rp + node + 1);
    float4 acc = make_float4(0.f, 0.f, 0.f, 0.f);

    for (int base = beg; base < end; base += 32) {
        int n = min(32, end - base);
        int sidx = (base + lane < end) ? __ldg(csr + base + lane) : 0;
        int j = 0;
        for (; j + 8 <= n; j += 8) {
            int s0 = __shfl_sync(0xffffffffu, sidx, j);
            int s1 = __shfl_sync(0xffffffffu, sidx, j + 1);
            int s2 = __shfl_sync(0xffffffffu, sidx, j + 2);
            int s3 = __shfl_sync(0xffffffffu, sidx, j + 3);
            int s4 = __shfl_sync(0xffffffffu, sidx, j + 4);
            int s5 = __shfl_sync(0xffffffffu, sidx, j + 5);
            int s6 = __shfl_sync(0xffffffffu, sidx, j + 6);
            int s7 = __shfl_sync(0xffffffffu, sidx, j + 7);
            uint2 v0 = __ldg(pk + (size_t)s0 * 32 + lane);
            uint2 v1 = __ldg(pk + (size_t)s1 * 32 + lane);
            uint2 v2 = __ldg(pk + (size_t)s2 * 32 + lane);
            uint2 v3 = __ldg(pk + (size_t)s3 * 32 + lane);
            uint2 v4 = __ldg(pk + (size_t)s4 * 32 + lane);
            uint2 v5 = __ldg(pk + (size_t)s5 * 32 + lane);
            uint2 v6 = __ldg(pk + (size_t)s6 * 32 + lane);
            uint2 v7 = __ldg(pk + (size_t)s7 * 32 + lane);
            // pairwise fp16 add, fp32 accumulate per pair (same depth as R8)
            h4_acc(h4_add(v0, v1), acc);
            h4_acc(h4_add(v2, v3), acc);
            h4_acc(h4_add(v4, v5), acc);
            h4_acc(h4_add(v6, v7), acc);
        }
        for (; j < n; j++) {
            int s0 = __shfl_sync(0xffffffffu, sidx, j);
            h4_acc(__ldg(pk + (size_t)s0 * 32 + lane), acc);
        }
    }

    int deg = end - beg;
    float inv = (deg > 0) ? (1.f / (float)deg) : 0.f;
    acc.x *= inv; acc.y *= inv; acc.z *= inv; acc.w *= inv;

    __stcs(mean + (size_t)node * 32 + lane, f4_to_h4(acc));
}

// ---------------- WMMA GEMM (all 3 spaces in one launch, z = space) ------------
__global__ void __launch_bounds__(256)
gemm_wmma3(const __half* __restrict__ em, const __half* __restrict__ bm,
           const __half* __restrict__ sm, const __half* __restrict__ Wth,
           const float* __restrict__ b_e, const float* __restrict__ b_b,
           const float* __restrict__ b_s, float* __restrict__ out,
           const int* __restrict__ rp) {
    extern __shared__ char sh[];
    __half* Xs = (__half*)sh;                       // [128][136]
    __half* Ws = (__half*)(sh + GTILE * LDH * 2);   // [128][136]
    float*  Os = (float*)sh;                        // [128][128] aliases Xs/Ws

    int z = blockIdx.z;
    const __half* X    = (z == 0) ? em : (z == 1) ? bm : sm;
    const __half* Wt   = Wth + z * DIM * DIM;
    const float*  bias = (z == 0) ? b_e : (z == 1) ? b_b : b_s;
    float*        Y    = out + (size_t)z * N_NODES * DIM;

    int tid = threadIdx.x;
    int warp = tid >> 5, lane = tid & 31;
    int row0 = blockIdx.x * GTILE;

    const uint2* X2 = (const uint2*)X;
    #pragma unroll
    for (int i = 0; i < 16; i++) {
        int f = tid + 256 * i;
        int r = f >> 5, c4 = f & 31;
        int gr = row0 + r;
        uint2 v = make_uint2(0u, 0u);
        if (gr < N_NODES) v = __ldcs(X2 + (size_t)gr * 32 + c4);   // read-once stream
        *(uint2*)(Xs + r * LDH + c4 * 4) = v;
    }
    const uint2* W2 = (const uint2*)Wt;
    #pragma unroll
    for (int i = 0; i < 16; i++) {
        int f = tid + 256 * i;
        int r = f >> 5, c4 = f & 31;
        *(uint2*)(Ws + r * LDH + c4 * 4) = __ldg(W2 + f);          // reused: keep cached
    }
    __syncthreads();

    wmma::fragment<wmma::accumulator, 16, 16, 16, float> acc[8];
    #pragma unroll
    for (int n = 0; n < 8; n++) wmma::fill_fragment(acc[n], 0.f);

    #pragma unroll
    for (int k = 0; k < 8; k++) {
        wmma::fragment<wmma::matrix_a, 16, 16, 16, __half, wmma::row_major> a;
        wmma::load_matrix_sync(a, Xs + (warp * 16) * LDH + k * 16, LDH);
        #pragma unroll
        for (int n = 0; n < 8; n++) {
            wmma::fragment<wmma::matrix_b, 16, 16, 16, __half, wmma::row_major> b;
            wmma::load_matrix_sync(b, Ws + (k * 16) * LDH + n * 16, LDH);
            wmma::mma_sync(acc[n], a, b, acc[n]);
        }
    }
    __syncthreads();

    #pragma unroll
    for (int n = 0; n < 8; n++)
        wmma::store_matrix_sync(Os + (warp * 16) * GTILE + n * 16, acc[n], GTILE,
                                wmma::mem_row_major);
    __syncthreads();

    float4 bv = __ldg((const float4*)bias + lane);
    #pragma unroll
    for (int i = 0; i < 16; i++) {
        int r = warp * 16 + i;
        int gr = row0 + r;
        if (gr >= N_NODES) break;
        float4 v = *(const float4*)(Os + r * GTILE + lane * 4);
        v.x += bv.x; v.y += bv.y; v.z += bv.z; v.w += bv.w;
        if (z == 0) {
            v.x = (v.x >= 0.f) ? v.x : 0.2f * v.x;
            v.y = (v.y >= 0.f) ? v.y : 0.2f * v.y;
            v.z = (v.z >= 0.f) ? v.z : 0.2f * v.z;
            v.w = (v.w >= 0.f) ? v.w : 0.2f * v.w;
        } else {
            int deg = __ldg(rp + gr + 1) - __ldg(rp + gr);
            if (deg == 0) {
                v = make_float4(0.f, 0.f, 0.f, 0.f);
            } else {
                float ss = v.x*v.x + v.y*v.y + v.z*v.z + v.w*v.w;
                #pragma unroll
                for (int o = 16; o; o >>= 1) ss += __shfl_xor_sync(0xffffffffu, ss, o);
                float ns = fmaxf(sqrtf(ss), EPSF);
                float sc = (z == 1) ? (tanhf(ns) / ns) : (1.f / ns);
                v.x *= sc; v.y *= sc; v.z *= sc; v.w *= sc;
            }
        }
        __stcs((float4*)Y + (size_t)gr * 32 + lane, v);            // write-once stream
    }
}

// ---------------- launch --------------------------------------------------------
extern "C" void kernel_launch(void* const* d_in, const int* in_sizes, int n_in,
                              void* d_out, int out_size) {
    const float* e_emb = (const float*)d_in[0];
    const float* b_emb = (const float*)d_in[1];
    const float* s_emb = (const float*)d_in[2];
    const float* W_e   = (const float*)d_in[3];
    const float* b_e   = (const float*)d_in[4];
    const float* W_b   = (const float*)d_in[5];
    const float* b_b   = (const float*)d_in[6];
    const float* W_s   = (const float*)d_in[7];
    const float* b_s   = (const float*)d_in[8];
    const int*   src   = (const int*)d_in[9];
    const int*   dst   = (const int*)d_in[10];

    float* out = (float*)d_out;

    __half *packe, *packb, *packs, *emean, *bmean, *smean, *Wth;
    int *counts, *rowptr, *cursor, *csr;
    cudaGetSymbolAddress((void**)&packe,  g_packe);
    cudaGetSymbolAddress((void**)&packb,  g_packb);
    cudaGetSymbolAddress((void**)&packs,  g_packs);
    cudaGetSymbolAddress((void**)&emean,  g_emean);
    cudaGetSymbolAddress((void**)&bmean,  g_bmean);
    cudaGetSymbolAddress((void**)&smean,  g_smean);
    cudaGetSymbolAddress((void**)&Wth,    g_Wth);
    cudaGetSymbolAddress((void**)&counts, g_counts);
    cudaGetSymbolAddress((void**)&rowptr, g_rowptr);
    cudaGetSymbolAddress((void**)&cursor, g_cursor);
    cudaGetSymbolAddress((void**)&csr,    g_csr);
    int* status = counts + N_NODES;

    const int GSMEM = 2 * GTILE * LDH * 2;   // 69632 B
    cudaFuncSetAttribute(gemm_wmma3, cudaFuncAttributeMaxDynamicSharedMemorySize, GSMEM);

    // counts/status are zero at entry: zero-initialized at module load, then
    // re-zeroed inside scatter_pack_kernel every launch (graph-replay invariant).
    hist_kernel<<<2048, 256>>>((const int4*)dst, counts);
    scan_lookback<<<NBLK, 256>>>(counts, rowptr, cursor, status);
    scatter_pack_kernel<<<MERG_BLOCKS, 256>>>((const int4*)src, (const int4*)dst,
                                              cursor, csr,
                                              e_emb, b_emb, s_emb,
                                              packe, packb, packs,
                                              W_e, W_b, W_s, Wth, counts);

    // three agg passes, one space each: 25.6 MB gather set stays L2-resident
    const int AGG_BLOCKS = (N_NODES * 32 + 63) / 64;   // 50000
    agg_space<<<AGG_BLOCKS, 64>>>((const uint2*)packe, (uint2*)emean, csr, rowptr);
    agg_space<<<AGG_BLOCKS, 64>>>((const uint2*)packb, (uint2*)bmean, csr, rowptr);
    agg_space<<<AGG_BLOCKS, 64>>>((const uint2*)packs, (uint2*)smean, csr, rowptr);

    dim3 gg((N_NODES + GTILE - 1) / GTILE, 1, 3);   // 782 x 1 x 3
    gemm_wmma3<<<gg, 256, GSMEM>>>(emean, bmean, smean, Wth, b_e, b_b, b_s, out, rowptr);
}